// round 7
// baseline (speedup 1.0000x reference)
#include <cuda_runtime.h>
#include <stdint.h>

#define L_DIM 1024
#define MAX_B 64
#define N_SHIFT 10

// Per-row contiguous valid interval [lo, hi]:
// out[b][i][j] = 1 iff lo[b][i] <= j <= hi[b][i].
__device__ int2 g_lohi[MAX_B * L_DIM];

// Kernel 1: compute per-row reach. One block per batch, 1024 threads (one per i).
__global__ __launch_bounds__(L_DIM) void reach_kernel(const int* __restrict__ mask) {
    __shared__ int sm[L_DIM];
    const int b = blockIdx.x;
    const int t = threadIdx.x;

    sm[t] = mask[b * L_DIM + t];
    __syncthreads();

    // Forward: include j = t+s iff sm[t+1 .. t+s] all zero.
    int hi = t;
    #pragma unroll
    for (int s = 1; s <= N_SHIFT; ++s) {
        const int p = t + s;
        if (p >= L_DIM || sm[p] != 0) break;
        hi = p;
    }
    // Backward: include j = t-s iff sm[t-s+1 .. t] all zero.
    int lo = t;
    #pragma unroll
    for (int s = 1; s <= N_SHIFT; ++s) {
        const int j = t - s;
        if (j < 0 || sm[j + 1] != 0) break;
        lo = j;
    }
    g_lohi[b * L_DIM + t] = make_int2(lo, hi);
}

// Kernel 2: fill. Block handles 4 rows of one batch; 256 threads; each thread
// stores 4 consecutive float4s (16 floats, 64B) within one row. Common path:
// one broadcast int2 load + 2 compares + 4 zero STG.128s.
__global__ __launch_bounds__(256) void fill_kernel(float* __restrict__ out) {
    const int b  = blockIdx.y;
    const int i  = (blockIdx.x << 2) + (threadIdx.x >> 6);  // row
    const int q  = (threadIdx.x & 63) << 2;                 // float4 index base (0..252)
    const int j0 = q << 2;                                  // element index (0..1008)

    const int2 lh = g_lohi[b * L_DIM + i];

    float4* __restrict__ orow =
        reinterpret_cast<float4*>(out + (((size_t)b << 10) + i) * (size_t)L_DIM);

    const float4 vz = make_float4(0.f, 0.f, 0.f, 0.f);

    if (j0 + 15 < lh.x || j0 > lh.y) {
        // Entire 16-element span out of band: pure zero stores.
        orow[q + 0] = vz;
        orow[q + 1] = vz;
        orow[q + 2] = vz;
        orow[q + 3] = vz;
    } else {
        #pragma unroll
        for (int u = 0; u < 4; ++u) {
            const int e = j0 + (u << 2);
            float4 v;
            v.x = (e + 0 >= lh.x && e + 0 <= lh.y) ? 1.f : 0.f;
            v.y = (e + 1 >= lh.x && e + 1 <= lh.y) ? 1.f : 0.f;
            v.z = (e + 2 >= lh.x && e + 2 <= lh.y) ? 1.f : 0.f;
            v.w = (e + 3 >= lh.x && e + 3 <= lh.y) ? 1.f : 0.f;
            orow[q + u] = v;
        }
    }
}

extern "C" void kernel_launch(void* const* d_in, const int* in_sizes, int n_in,
                              void* d_out, int out_size) {
    const int* mask = (const int*)d_in[0];
    float* out = (float*)d_out;

    const int B = in_sizes[0] / L_DIM;   // 32

    reach_kernel<<<B, L_DIM>>>(mask);
    dim3 grid(L_DIM / 4, B);             // 4 rows per block
    fill_kernel<<<grid, 256>>>(out);
}

// round 12
// speedup vs baseline: 1.3760x; 1.3760x over previous
#include <cuda_runtime.h>
#include <stdint.h>

#define L_DIM 1024
#define N_SHIFT 10

// out[b][i][j] = 1.0f iff |i-j| <= 10 and mask[b][p]==0 for all p in
// (min(i,j), max(i,j)].  Per row the valid set is a contiguous interval
// [lo, hi] around i.
//
// Zeros: cudaMemsetAsync memset node (driver fill path).
// Ones (~1.7 MB): one warp per row; lanes 0..31 map to j = i-10 .. i+21;
// one ballot gives the blocked-bitmap; clz/ffs give the reach.
//
// Clamps (each fixed a real bug):
//   fwd  <= N_SHIFT  (lanes 21..31 hold real mask data past the band — R7 bug)
//   back <= N_SHIFT
//   back <= i        (backward run may not include mask[0]'s lane; without
//                     this, an all-zero prefix gives lo = -1 and an OOB
//                     store at rowbase-1 — R8 bug)
__global__ __launch_bounds__(256) void band_kernel(const int* __restrict__ mask,
                                                   float* __restrict__ out) {
    const int warp = threadIdx.x >> 5;
    const int lane = threadIdx.x & 31;
    const int i = (blockIdx.x << 3) + warp;   // row
    const int b = blockIdx.y;                 // batch

    const int* __restrict__ mrow = mask + (size_t)b * L_DIM;

    // lane -> j = i + (lane - 10).
    const int j = i + lane - N_SHIFT;
    int m = 1;                                // OOB treated as blocked
    if (j >= 0 && j < L_DIM) m = mrow[j];

    const unsigned bits = __ballot_sync(0xFFFFFFFFu, m != 0);

    // Backward reach: consecutive zeros at lanes 10, 9, 8, ...
    const unsigned x = bits << 21;            // lane10 -> bit31
    int back = __clz(x);
    if (back > N_SHIFT) back = N_SHIFT;
    if (back > i)       back = i;             // reach cannot pass j=0

    // Forward reach: consecutive zeros at lanes 11, 12, ...
    const unsigned y = bits >> 11;            // lane11 -> bit0
    int fwd = (y == 0u) ? N_SHIFT : (__ffs(y) - 1);
    if (fwd > N_SHIFT) fwd = N_SHIFT;

    const int lo = i - back;
    const int hi = i + fwd;

    if (j >= lo && j <= hi && j >= 0 && j < L_DIM) {
        out[(((size_t)b << 10) + i) * (size_t)L_DIM + j] = 1.0f;
    }
}

extern "C" void kernel_launch(void* const* d_in, const int* in_sizes, int n_in,
                              void* d_out, int out_size) {
    const int* mask = (const int*)d_in[0];
    float* out = (float*)d_out;

    const int B = in_sizes[0] / L_DIM;        // 32

    // Zeros: driver memset node (graph-capturable).
    cudaMemsetAsync(d_out, 0, (size_t)out_size * sizeof(float));

    // Ones: one warp per row, 8 rows per 256-thread block.
    dim3 grid(L_DIM / 8, B);
    band_kernel<<<grid, 256>>>(mask, out);
}

// round 14
// speedup vs baseline: 1.5638x; 1.1365x over previous
#include <cuda_runtime.h>
#include <stdint.h>

#define L_DIM        1024
#define N_SHIFT      10
#define NBUF         4
#define ROWS_PER_CTA 16
#define ROW_BYTES    (L_DIM * 4)

// out[b][i][j] = 1.0f iff |i-j| <= 10 and mask[b][p]==0 for all p in
// (min(i,j), max(i,j)].  Per row: contiguous interval [lo, hi] around i.
//
// One-pass TMA-store kernel: each warp builds 4KB rows in rotating SMEM
// buffers (zeros persist; only band cells are written/cleared) and emits
// them via cp.async.bulk shared->global, which runs at the same LTS-cap
// bandwidth as the driver memset path (~6.1+ TB/s measured) — fusing the
// memset + band passes of R12 into one.
__global__ __launch_bounds__(32) void band_tma_kernel(const int* __restrict__ mask,
                                                      float* __restrict__ out) {
    __shared__ __align__(128) float buf[NBUF][L_DIM];
    const int lane = threadIdx.x;

    // Zero all buffers once (float4 stores).
    {
        float4* bv = reinterpret_cast<float4*>(&buf[0][0]);
        const float4 z = make_float4(0.f, 0.f, 0.f, 0.f);
        #pragma unroll
        for (int k = lane; k < NBUF * L_DIM / 4; k += 32) bv[k] = z;
    }
    __syncwarp();

    const int base = blockIdx.x * ROWS_PER_CTA;   // flattened row index b*L + i

    for (int it = 0; it < ROWS_PER_CTA; ++it) {
        const int flat = base + it;
        const int i = flat & (L_DIM - 1);
        const int b = flat >> 10;
        float* __restrict__ srow = buf[it & (NBUF - 1)];

        if (it >= NBUF) {
            // Ensure this buffer's previous TMA store (issued NBUF rows ago)
            // has drained: <= NBUF-1 groups pending leaves it complete.
            if (lane == 0)
                asm volatile("cp.async.bulk.wait_group %0;" :: "n"(NBUF - 1) : "memory");
            __syncwarp();
            // Clear the previous occupant's 32-cell window (superset of its 1s).
            const int pi = (flat - NBUF) & (L_DIM - 1);
            const int jo = pi + lane - N_SHIFT;
            if (jo >= 0 && jo < L_DIM) srow[jo] = 0.0f;
        }

        // --- Band interval via ballot (verified R12 logic, all clamps) ---
        const int* __restrict__ mrow = mask + ((size_t)b << 10);
        const int j = i + lane - N_SHIFT;          // lane -> j = i-10 .. i+21
        int m = 1;                                  // OOB treated as blocked
        if (j >= 0 && j < L_DIM) m = mrow[j];
        const unsigned bits = __ballot_sync(0xFFFFFFFFu, m != 0);

        const unsigned x = bits << 21;              // lane10 (= mask[i]) -> bit31
        int back = __clz(x);
        if (back > N_SHIFT) back = N_SHIFT;
        if (back > i)       back = i;               // reach cannot pass j=0

        const unsigned y = bits >> 11;              // lane11 -> bit0
        int fwd = (y == 0u) ? N_SHIFT : (__ffs(y) - 1);
        if (fwd > N_SHIFT) fwd = N_SHIFT;           // lanes 21..31 hold real data

        if (j >= i - back && j <= i + fwd) srow[j] = 1.0f;   // j in [0,L) guaranteed
        __syncwarp();

        // --- Emit the 4KB row via bulk async store ---
        if (lane == 0) {
            asm volatile("fence.proxy.async.shared::cta;" ::: "memory");
            uint32_t saddr;
            asm("{ .reg .u64 t; cvta.to.shared.u64 t, %1; cvt.u32.u64 %0, t; }"
                : "=r"(saddr) : "l"(srow));
            asm volatile("cp.async.bulk.global.shared::cta.bulk_group [%0], [%1], %2;"
                         :: "l"(out + ((size_t)flat << 10)), "r"(saddr), "r"(ROW_BYTES)
                         : "memory");
            asm volatile("cp.async.bulk.commit_group;" ::: "memory");
        }
    }

    // Drain all outstanding stores before the buffers go out of scope.
    if (lane == 0)
        asm volatile("cp.async.bulk.wait_group 0;" ::: "memory");
}

extern "C" void kernel_launch(void* const* d_in, const int* in_sizes, int n_in,
                              void* d_out, int out_size) {
    const int* mask = (const int*)d_in[0];
    float* out = (float*)d_out;

    const int rows = in_sizes[0];                 // B * L = 32768
    const int ncta = rows / ROWS_PER_CTA;         // 2048

    band_tma_kernel<<<ncta, 32>>>(mask, out);
}